// round 13
// baseline (speedup 1.0000x reference)
#include <cuda_runtime.h>
#include <cuda_bf16.h>

// Problem constants (fixed by the reference)
#define N_USERS 100000
#define N_ITEMS 100000
#define NTOT    (N_USERS + N_ITEMS)   // 200000
#define EMBD    64
#define NNZ_E   1000000
#define NELEMS  (NTOT * EMBD)         // 12,800,000 floats

// Fixed-capacity row buckets: Poisson(5) degrees, 16 slots covers ~all rows;
// the rare deg>16 edges spill to an overflow list (handled exactly).
#define CAP    16
#define OVCAP  65536

// Allocation-free scratch (__device__ globals)
__device__ int   g_counts[NTOT];           // per-row degree (full, may exceed CAP)
__device__ int2  g_sedge[NTOT * CAP];      // {col, f32 bits of val} per slot
__device__ int   g_ovcount;
__device__ int4  g_ovlist[OVCAP];          // {row, col, f32 bits of val, pad}
__device__ float g_y1[NELEMS];
__device__ float g_y2[NELEMS];

// Virtual concat(user_w, item_w): for materialized x pass (x, x + N_USERS*EMBD)
// and the select reduces to x + c*EMBD.
__device__ __forceinline__ const float* rowptr(const float* __restrict__ u,
                                               const float* __restrict__ it,
                                               int c)
{
    return (c < N_USERS) ? (u + (long long)c * EMBD)
                         : (it + (long long)(c - N_USERS) * EMBD);
}

__device__ __forceinline__ void fma4(float4& acc, float v, float4 x)
{
    acc.x += v * x.x; acc.y += v * x.y; acc.z += v * x.z; acc.w += v * x.w;
}

// ---------------------------------------------------------------------------
// bucket: one pass, no scan. pos = atomicAdd(deg[r]); slot or overflow list.
// ---------------------------------------------------------------------------
__global__ void k_bucket(const int*   __restrict__ rows,
                         const int*   __restrict__ cols,
                         const float* __restrict__ vals)
{
    int e = blockIdx.x * blockDim.x + threadIdx.x;
    if (e >= NNZ_E) return;
    int   r = __ldg(rows + e);
    int   c = __ldg(cols + e);
    float v = __ldg(vals + e);
    int pos = atomicAdd(&g_counts[r], 1);
    if (pos < CAP) {
        g_sedge[r * CAP + pos] = make_int2(c, __float_as_int(v));
    } else {
        int o = atomicAdd(&g_ovcount, 1);
        if (o < OVCAP) g_ovlist[o] = make_int4(r, c, __float_as_int(v), 0);
    }
}

// ---------------------------------------------------------------------------
// pull SpMM: 16 threads per output row, thread p owns float4 slot p.
// 4-edge unroll: one 32B broadcast edge load -> 4 independent gathers (MLP=4).
// ONE plain 16B store. No atomics, no pre-zeroing.
// ---------------------------------------------------------------------------
__global__ void k_pull_spmm(const float* __restrict__ xu,
                            const float* __restrict__ xi,
                            float*       __restrict__ y)
{
    long long tid = (long long)blockIdx.x * blockDim.x + threadIdx.x;
    int r = (int)(tid >> 4);
    int p = (int)(tid & 15);
    if (r >= NTOT) return;

    int n = min(__ldg(&g_counts[r]), CAP);
    const int2* ep = g_sedge + r * CAP;

    float4 acc = make_float4(0.f, 0.f, 0.f, 0.f);
    int j = 0;
    for (; j + 4 <= n; j += 4) {
        int2 e0 = __ldg(ep + j + 0);
        int2 e1 = __ldg(ep + j + 1);
        int2 e2 = __ldg(ep + j + 2);
        int2 e3 = __ldg(ep + j + 3);
        float4 x0 = __ldg((const float4*)rowptr(xu, xi, e0.x) + p);
        float4 x1 = __ldg((const float4*)rowptr(xu, xi, e1.x) + p);
        float4 x2 = __ldg((const float4*)rowptr(xu, xi, e2.x) + p);
        float4 x3 = __ldg((const float4*)rowptr(xu, xi, e3.x) + p);
        fma4(acc, __int_as_float(e0.y), x0);
        fma4(acc, __int_as_float(e1.y), x1);
        fma4(acc, __int_as_float(e2.y), x2);
        fma4(acc, __int_as_float(e3.y), x3);
    }
    for (; j < n; j++) {
        int2 e0 = __ldg(ep + j);
        float4 x0 = __ldg((const float4*)rowptr(xu, xi, e0.x) + p);
        fma4(acc, __int_as_float(e0.y), x0);
    }
    ((float4*)(y + (long long)r * EMBD))[p] = acc;
}

// ---------------------------------------------------------------------------
// Final layer fused with mean: out[r] = 0.25*(x0[r] + y1[r] + y2[r] + (A@y2)[r])
// ---------------------------------------------------------------------------
__global__ void k_pull_final(const float* __restrict__ y2u,   // = y2
                             const float* __restrict__ y2i,   // = y2 + off
                             const float* __restrict__ user_w,
                             const float* __restrict__ item_w,
                             const float* __restrict__ y1,
                             float*       __restrict__ out)
{
    long long tid = (long long)blockIdx.x * blockDim.x + threadIdx.x;
    int r = (int)(tid >> 4);
    int p = (int)(tid & 15);
    if (r >= NTOT) return;

    int n = min(__ldg(&g_counts[r]), CAP);
    const int2* ep = g_sedge + r * CAP;

    float4 acc = make_float4(0.f, 0.f, 0.f, 0.f);
    int j = 0;
    for (; j + 4 <= n; j += 4) {
        int2 e0 = __ldg(ep + j + 0);
        int2 e1 = __ldg(ep + j + 1);
        int2 e2 = __ldg(ep + j + 2);
        int2 e3 = __ldg(ep + j + 3);
        float4 x0 = __ldg((const float4*)rowptr(y2u, y2i, e0.x) + p);
        float4 x1 = __ldg((const float4*)rowptr(y2u, y2i, e1.x) + p);
        float4 x2 = __ldg((const float4*)rowptr(y2u, y2i, e2.x) + p);
        float4 x3 = __ldg((const float4*)rowptr(y2u, y2i, e3.x) + p);
        fma4(acc, __int_as_float(e0.y), x0);
        fma4(acc, __int_as_float(e1.y), x1);
        fma4(acc, __int_as_float(e2.y), x2);
        fma4(acc, __int_as_float(e3.y), x3);
    }
    for (; j < n; j++) {
        int2 e0 = __ldg(ep + j);
        float4 x0 = __ldg((const float4*)rowptr(y2u, y2i, e0.x) + p);
        fma4(acc, __int_as_float(e0.y), x0);
    }

    const float* x0r = rowptr(user_w, item_w, r);
    float4 x = __ldg((const float4*)x0r + p);
    float4 a = __ldg((const float4*)(y1  + (long long)r * EMBD) + p);
    float4 b = __ldg((const float4*)(y2u + (long long)r * EMBD) + p);

    float4 o;
    o.x = (x.x + a.x + b.x + acc.x) * 0.25f;
    o.y = (x.y + a.y + b.y + acc.y) * 0.25f;
    o.z = (x.z + a.z + b.z + acc.z) * 0.25f;
    o.w = (x.w + a.w + b.w + acc.w) * 0.25f;
    ((float4*)(out + (long long)r * EMBD))[p] = o;
}

// ---------------------------------------------------------------------------
// overflow: push the (rare) deg>CAP edges with atomics. Runs AFTER the pull
// kernel that wrote y (plain stores), so add order is correct.
// ---------------------------------------------------------------------------
__global__ void k_overflow(const float* __restrict__ xu,
                           const float* __restrict__ xi,
                           float*       __restrict__ y,
                           float scale)
{
    int n = min(g_ovcount, OVCAP);
    int total = n * 16;
    int stride = gridDim.x * blockDim.x;
    for (int i = blockIdx.x * blockDim.x + threadIdx.x; i < total; i += stride) {
        int e = i >> 4;
        int p = i & 15;
        int4 E = g_ovlist[e];
        float4 xv = __ldg((const float4*)rowptr(xu, xi, E.y) + p);
        float v = __int_as_float(E.z) * scale;
        xv.x *= v; xv.y *= v; xv.z *= v; xv.w *= v;
        atomicAdd((float4*)(y + (long long)E.x * EMBD) + p, xv);
    }
}

extern "C" void kernel_launch(void* const* d_in, const int* in_sizes, int n_in,
                              void* d_out, int out_size)
{
    const float* user_w = (const float*)d_in[0];
    const float* item_w = (const float*)d_in[1];
    const float* vals   = (const float*)d_in[2];
    const int*   rows   = (const int*)d_in[3];
    const int*   cols   = (const int*)d_in[4];
    float*       out    = (float*)d_out;

    int *counts, *ovcount;
    float *y1, *y2;
    cudaGetSymbolAddress((void**)&counts,  g_counts);
    cudaGetSymbolAddress((void**)&ovcount, g_ovcount);
    cudaGetSymbolAddress((void**)&y1,      g_y1);
    cudaGetSymbolAddress((void**)&y2,      g_y2);

    const int TB = 256;
    const int gridEdge = (NNZ_E + TB - 1) / TB;         // 3907
    const int gridSpmm = (NTOT * 16 + TB - 1) / TB;     // 12500

    // ---- build: 2 memsets + ONE bucketing pass (no scan) ----
    cudaMemsetAsync(counts, 0, NTOT * sizeof(int));
    cudaMemsetAsync(ovcount, 0, sizeof(int));
    k_bucket<<<gridEdge, TB>>>(rows, cols, vals);

    const float* y1i = y1 + (long long)N_USERS * EMBD;  // two-pointer trick
    const float* y2i = y2 + (long long)N_USERS * EMBD;

    // y1 = A @ x0
    k_pull_spmm<<<gridSpmm, TB>>>(user_w, item_w, y1);
    k_overflow<<<32, TB>>>(user_w, item_w, y1, 1.0f);

    // y2 = A @ y1
    k_pull_spmm<<<gridSpmm, TB>>>(y1, y1i, y2);
    k_overflow<<<32, TB>>>(y1, y1i, y2, 1.0f);

    // out = 0.25*(x0 + y1 + y2 + A @ y2)
    k_pull_final<<<gridSpmm, TB>>>(y2, y2i, user_w, item_w, y1, out);
    k_overflow<<<32, TB>>>(y2, y2i, out, 0.25f);
}

// round 14
// speedup vs baseline: 1.2794x; 1.2794x over previous
#include <cuda_runtime.h>
#include <cuda_bf16.h>

// Problem constants (fixed by the reference)
#define N_USERS 100000
#define N_ITEMS 100000
#define NTOT    (N_USERS + N_ITEMS)   // 200000
#define EMBD    64
#define NNZ_E   1000000
#define NELEMS  (NTOT * EMBD)         // 12,800,000 floats

// Fixed-capacity row buckets (Poisson(5) degrees; deg>16 spills to overflow)
#define CAP    16
#define OVCAP  65536

// Allocation-free scratch (__device__ globals)
__device__ int   g_counts[NTOT];           // per-row degree (may exceed CAP)
__device__ int2  g_sedge[NTOT * CAP];      // {col, f32 bits of val}; 128B/row
__device__ int   g_ovcount;
__device__ int4  g_ovlist[OVCAP];          // {row, col, f32 bits of val, pad}
__device__ float g_y1[NELEMS];
__device__ float g_y2[NELEMS];

__device__ __forceinline__ const float* rowptr(const float* __restrict__ u,
                                               const float* __restrict__ it,
                                               int c)
{
    return (c < N_USERS) ? (u + (long long)c * EMBD)
                         : (it + (long long)(c - N_USERS) * EMBD);
}

__device__ __forceinline__ void fma4(float4& acc, float v, float4 x)
{
    acc.x += v * x.x; acc.y += v * x.y; acc.z += v * x.z; acc.w += v * x.w;
}

// ---------------------------------------------------------------------------
// bucket: one pass, no scan.
// ---------------------------------------------------------------------------
__global__ void k_bucket(const int*   __restrict__ rows,
                         const int*   __restrict__ cols,
                         const float* __restrict__ vals)
{
    int e = blockIdx.x * blockDim.x + threadIdx.x;
    if (e >= NNZ_E) return;
    int   r = __ldg(rows + e);
    int   c = __ldg(cols + e);
    float v = __ldg(vals + e);
    int pos = atomicAdd(&g_counts[r], 1);
    if (pos < CAP) {
        g_sedge[r * CAP + pos] = make_int2(c, __float_as_int(v));
    } else {
        int o = atomicAdd(&g_ovcount, 1);
        if (o < OVCAP) g_ovlist[o] = make_int4(r, c, __float_as_int(v), 0);
    }
}

// ---------------------------------------------------------------------------
// Flat-8 gather core: preload 8 edges (4 independent int4 loads, always
// in-bounds within the row's 128B bucket), then 8 CLAMPED branch-free gathers
// (invalid slots clamp to col 0 / v=0 -> L1-resident, ~zero LTS cost).
// Chain: count -> edges(MLP4) -> gathers(MLP8) -> store.
// ---------------------------------------------------------------------------
#define GATHER8(XU, XI, ACC, NC)                                              \
    {                                                                         \
        int4 q0 = __ldg(eb + 0);                                              \
        int4 q1 = __ldg(eb + 1);                                              \
        int4 q2 = __ldg(eb + 2);                                              \
        int4 q3 = __ldg(eb + 3);                                              \
        int   c0 = (0 < NC) ? q0.x : 0;  float v0 = (0 < NC) ? __int_as_float(q0.y) : 0.f; \
        int   c1 = (1 < NC) ? q0.z : 0;  float v1 = (1 < NC) ? __int_as_float(q0.w) : 0.f; \
        int   c2 = (2 < NC) ? q1.x : 0;  float v2 = (2 < NC) ? __int_as_float(q1.y) : 0.f; \
        int   c3 = (3 < NC) ? q1.z : 0;  float v3 = (3 < NC) ? __int_as_float(q1.w) : 0.f; \
        int   c4 = (4 < NC) ? q2.x : 0;  float v4 = (4 < NC) ? __int_as_float(q2.y) : 0.f; \
        int   c5 = (5 < NC) ? q2.z : 0;  float v5 = (5 < NC) ? __int_as_float(q2.w) : 0.f; \
        int   c6 = (6 < NC) ? q3.x : 0;  float v6 = (6 < NC) ? __int_as_float(q3.y) : 0.f; \
        int   c7 = (7 < NC) ? q3.z : 0;  float v7 = (7 < NC) ? __int_as_float(q3.w) : 0.f; \
        float4 x0 = __ldg((const float4*)rowptr(XU, XI, c0) + p);             \
        float4 x1 = __ldg((const float4*)rowptr(XU, XI, c1) + p);             \
        float4 x2 = __ldg((const float4*)rowptr(XU, XI, c2) + p);             \
        float4 x3 = __ldg((const float4*)rowptr(XU, XI, c3) + p);             \
        float4 x4 = __ldg((const float4*)rowptr(XU, XI, c4) + p);             \
        float4 x5 = __ldg((const float4*)rowptr(XU, XI, c5) + p);             \
        float4 x6 = __ldg((const float4*)rowptr(XU, XI, c6) + p);             \
        float4 x7 = __ldg((const float4*)rowptr(XU, XI, c7) + p);             \
        fma4(ACC, v0, x0); fma4(ACC, v1, x1);                                 \
        fma4(ACC, v2, x2); fma4(ACC, v3, x3);                                 \
        fma4(ACC, v4, x4); fma4(ACC, v5, x5);                                 \
        fma4(ACC, v6, x6); fma4(ACC, v7, x7);                                 \
    }

// Tail for rows with 8 < deg <= 16 (6.8% of rows)
#define GATHER_TAIL(XU, XI, ACC, NC)                                          \
    if (NC > 8) {                                                             \
        const int2* ep = (const int2*)eb;                                     \
        for (int j = 8; j < NC; j++) {                                        \
            int2 e0 = __ldg(ep + j);                                          \
            float4 xv = __ldg((const float4*)rowptr(XU, XI, e0.x) + p);       \
            fma4(ACC, __int_as_float(e0.y), xv);                              \
        }                                                                     \
    }

// ---------------------------------------------------------------------------
// pull SpMM: 16 threads per output row; ONE plain 16B store, no atomics.
// ---------------------------------------------------------------------------
__global__ void k_pull_spmm(const float* __restrict__ xu,
                            const float* __restrict__ xi,
                            float*       __restrict__ y)
{
    long long tid = (long long)blockIdx.x * blockDim.x + threadIdx.x;
    int r = (int)(tid >> 4);
    int p = (int)(tid & 15);
    if (r >= NTOT) return;

    int nc = min(__ldg(&g_counts[r]), CAP);
    const int4* eb = (const int4*)(g_sedge + r * CAP);

    float4 acc = make_float4(0.f, 0.f, 0.f, 0.f);
    GATHER8(xu, xi, acc, nc);
    GATHER_TAIL(xu, xi, acc, nc);
    ((float4*)(y + (long long)r * EMBD))[p] = acc;
}

// ---------------------------------------------------------------------------
// Final layer fused with mean: out[r] = 0.25*(x0[r] + y1[r] + y2[r] + (A@y2)[r])
// ---------------------------------------------------------------------------
__global__ void k_pull_final(const float* __restrict__ y2u,
                             const float* __restrict__ y2i,
                             const float* __restrict__ user_w,
                             const float* __restrict__ item_w,
                             const float* __restrict__ y1,
                             float*       __restrict__ out)
{
    long long tid = (long long)blockIdx.x * blockDim.x + threadIdx.x;
    int r = (int)(tid >> 4);
    int p = (int)(tid & 15);
    if (r >= NTOT) return;

    int nc = min(__ldg(&g_counts[r]), CAP);
    const int4* eb = (const int4*)(g_sedge + r * CAP);

    float4 acc = make_float4(0.f, 0.f, 0.f, 0.f);
    GATHER8(y2u, y2i, acc, nc);
    GATHER_TAIL(y2u, y2i, acc, nc);

    const float* x0r = rowptr(user_w, item_w, r);
    float4 x = __ldg((const float4*)x0r + p);
    float4 a = __ldg((const float4*)(y1  + (long long)r * EMBD) + p);
    float4 b = __ldg((const float4*)(y2u + (long long)r * EMBD) + p);

    float4 o;
    o.x = (x.x + a.x + b.x + acc.x) * 0.25f;
    o.y = (x.y + a.y + b.y + acc.y) * 0.25f;
    o.z = (x.z + a.z + b.z + acc.z) * 0.25f;
    o.w = (x.w + a.w + b.w + acc.w) * 0.25f;
    ((float4*)(out + (long long)r * EMBD))[p] = o;
}

// ---------------------------------------------------------------------------
// overflow: push the (rare) deg>CAP edges with atomics, after the pull store.
// ---------------------------------------------------------------------------
__global__ void k_overflow(const float* __restrict__ xu,
                           const float* __restrict__ xi,
                           float*       __restrict__ y,
                           float scale)
{
    int n = min(g_ovcount, OVCAP);
    int total = n * 16;
    int stride = gridDim.x * blockDim.x;
    for (int i = blockIdx.x * blockDim.x + threadIdx.x; i < total; i += stride) {
        int e = i >> 4;
        int p = i & 15;
        int4 E = g_ovlist[e];
        float4 xv = __ldg((const float4*)rowptr(xu, xi, E.y) + p);
        float v = __int_as_float(E.z) * scale;
        xv.x *= v; xv.y *= v; xv.z *= v; xv.w *= v;
        atomicAdd((float4*)(y + (long long)E.x * EMBD) + p, xv);
    }
}

extern "C" void kernel_launch(void* const* d_in, const int* in_sizes, int n_in,
                              void* d_out, int out_size)
{
    const float* user_w = (const float*)d_in[0];
    const float* item_w = (const float*)d_in[1];
    const float* vals   = (const float*)d_in[2];
    const int*   rows   = (const int*)d_in[3];
    const int*   cols   = (const int*)d_in[4];
    float*       out    = (float*)d_out;

    int *counts, *ovcount;
    float *y1, *y2;
    cudaGetSymbolAddress((void**)&counts,  g_counts);
    cudaGetSymbolAddress((void**)&ovcount, g_ovcount);
    cudaGetSymbolAddress((void**)&y1,      g_y1);
    cudaGetSymbolAddress((void**)&y2,      g_y2);

    const int TB = 256;
    const int gridEdge = (NNZ_E + TB - 1) / TB;         // 3907
    const int gridSpmm = (NTOT * 16 + TB - 1) / TB;     // 12500

    // ---- build: 2 memsets + ONE bucketing pass ----
    cudaMemsetAsync(counts, 0, NTOT * sizeof(int));
    cudaMemsetAsync(ovcount, 0, sizeof(int));
    k_bucket<<<gridEdge, TB>>>(rows, cols, vals);

    const float* y1i = y1 + (long long)N_USERS * EMBD;
    const float* y2i = y2 + (long long)N_USERS * EMBD;

    // y1 = A @ x0
    k_pull_spmm<<<gridSpmm, TB>>>(user_w, item_w, y1);
    k_overflow<<<32, TB>>>(user_w, item_w, y1, 1.0f);

    // y2 = A @ y1
    k_pull_spmm<<<gridSpmm, TB>>>(y1, y1i, y2);
    k_overflow<<<32, TB>>>(y1, y1i, y2, 1.0f);

    // out = 0.25*(x0 + y1 + y2 + A @ y2)
    k_pull_final<<<gridSpmm, TB>>>(y2, y2i, user_w, item_w, y1, out);
    k_overflow<<<32, TB>>>(y2, y2i, out, 0.25f);
}